// round 4
// baseline (speedup 1.0000x reference)
#include <cuda_runtime.h>

#define F 256
#define F4 (F / 4)                   // 64 float4 per row
#define TOTAL_ROWS (32 * 4096)       // B*T = 131072
#define TOTAL4 ((size_t)TOTAL_ROWS * F4)   // 8,388,608 float4
#define STATS_BLOCKS 1024
#define STATS_THREADS 256
#define STATS_ITERS 32               // TOTAL4 / (STATS_BLOCKS*STATS_THREADS), exact
#define EPS 1e-5f

// Scratch (no cudaMalloc allowed). Zero-initialized at module load;
// finalize_kernel restores zeros after each use, so every call/replay
// starts from a clean state without an init launch.
__device__ float g_sum[F];
__device__ float g_sumsq[F];
__device__ float g_count;            // = 64 * (#masked rows), exact in fp32 (< 2^23)
__device__ float g_scale[F];
__device__ float g_bias[F];

// ---------------------------------------------------------------------------
// Kernel 1: per-feature sum / sumsq. UNCONDITIONAL streaming read of x
// (128 MB @ ~6 TB/s beats any masked-gather variant), weighted by
// w = (mask>0). No control flow, no address dependence on the mask ->
// ptxas front-batches all LDG.128 (high MLP). Grid-stride with stride a
// multiple of 64 keeps each thread on a fixed feature group f4 = i&63.
// ---------------------------------------------------------------------------
__global__ void __launch_bounds__(STATS_THREADS)
stats_kernel(const float* __restrict__ x, const int* __restrict__ mask) {
    const int tid = threadIdx.x;
    const size_t i0     = (size_t)blockIdx.x * STATS_THREADS + tid;
    const size_t stride = (size_t)STATS_BLOCKS * STATS_THREADS;  // multiple of 64

    const float4* __restrict__ x4 = (const float4*)x;

    float4 acc  = make_float4(0.f, 0.f, 0.f, 0.f);
    float4 acc2 = make_float4(0.f, 0.f, 0.f, 0.f);
    float  cntf = 0.f;

#pragma unroll 1
    for (int it = 0; it < STATS_ITERS / 4; ++it) {
        float4 v[4];
        float  w[4];
#pragma unroll
        for (int u = 0; u < 4; ++u) {
            const size_t i = i0 + ((size_t)(it * 4 + u)) * stride;
            w[u] = (mask[i >> 6] > 0) ? 1.0f : 0.0f;   // L1-broadcast hit
            v[u] = __ldcs(&x4[i]);                     // streaming 16B load
        }
#pragma unroll
        for (int u = 0; u < 4; ++u) {
            float wx = w[u];
            acc.x  = fmaf(v[u].x, wx, acc.x);
            acc.y  = fmaf(v[u].y, wx, acc.y);
            acc.z  = fmaf(v[u].z, wx, acc.z);
            acc.w  = fmaf(v[u].w, wx, acc.w);
            float ax = v[u].x * wx, ay = v[u].y * wx;
            float az = v[u].z * wx, aw = v[u].w * wx;
            acc2.x = fmaf(ax, v[u].x, acc2.x);
            acc2.y = fmaf(ay, v[u].y, acc2.y);
            acc2.z = fmaf(az, v[u].z, acc2.z);
            acc2.w = fmaf(aw, v[u].w, acc2.w);
            cntf  += wx;
        }
    }

    // ---- intra-block reduction: 4 row-slots -> 1, then 1 atomic set/block ----
    const int f4  = tid & 63;
    const int sub = tid >> 6;

    __shared__ float4 s_sum[256];
    __shared__ float4 s_sq[256];
    __shared__ float  s_c[256];
    s_sum[tid] = acc;
    s_sq[tid]  = acc2;
    s_c[tid]   = cntf;
    __syncthreads();

    if (sub == 0) {
#pragma unroll
        for (int k = 1; k < 4; k++) {
            float4 a = s_sum[tid + 64 * k];
            float4 b = s_sq[tid + 64 * k];
            acc.x += a.x; acc.y += a.y; acc.z += a.z; acc.w += a.w;
            acc2.x += b.x; acc2.y += b.y; acc2.z += b.z; acc2.w += b.w;
            cntf += s_c[tid + 64 * k];
        }
        const int fb = f4 * 4;
        atomicAdd(&g_sum[fb + 0], acc.x);
        atomicAdd(&g_sum[fb + 1], acc.y);
        atomicAdd(&g_sum[fb + 2], acc.z);
        atomicAdd(&g_sum[fb + 3], acc.w);
        atomicAdd(&g_sumsq[fb + 0], acc2.x);
        atomicAdd(&g_sumsq[fb + 1], acc2.y);
        atomicAdd(&g_sumsq[fb + 2], acc2.z);
        atomicAdd(&g_sumsq[fb + 3], acc2.w);

        // reduce the 64 per-f4 counts to ONE atomic per block (avoid
        // single-address atomic serialization across 64K ops)
        s_c[tid] = cntf;
    }
    __syncthreads();
    if (tid < 32) {
        float c = s_c[tid] + s_c[tid + 32];
#pragma unroll
        for (int o = 16; o > 0; o >>= 1)
            c += __shfl_down_sync(0xffffffffu, c, o);
        if (tid == 0) atomicAdd(&g_count, c);
    }
}

// ---------------------------------------------------------------------------
// Kernel 2: finalize — fold mean/var/gamma/beta into per-feature affine,
// then RESET the accumulators so the next call/replay starts clean.
// ---------------------------------------------------------------------------
__global__ void finalize_kernel(const float* __restrict__ gamma,
                                const float* __restrict__ beta) {
    int f = threadIdx.x;
    float cnt  = g_count * (1.0f / 64.0f);   // each masked row counted by 64 threads
    float mean = g_sum[f] / cnt;
    float var  = g_sumsq[f] / cnt - mean * mean;
    float s    = rsqrtf(var + EPS) * gamma[f];
    g_scale[f] = s;
    g_bias[f]  = beta[f] - mean * s;
    // restore zero-state invariant
    g_sum[f]   = 0.f;
    g_sumsq[f] = 0.f;
    if (f == 0) g_count = 0.f;
}

// ---------------------------------------------------------------------------
// Kernel 3: apply. float4-vectorized; mask branch warp-uniform. Streaming
// hints on the 256 MB of bulk traffic. (~94% of mixed HBM floor.)
// ---------------------------------------------------------------------------
__global__ void __launch_bounds__(256) apply_kernel(const float* __restrict__ x,
                                                    const int*   __restrict__ mask,
                                                    float*       __restrict__ out) {
    const size_t i = (size_t)blockIdx.x * blockDim.x + threadIdx.x;  // float4 index
    const float4* __restrict__ x4 = (const float4*)x;
    float4* __restrict__ out4 = (float4*)out;

    const int row = (int)(i >> 6);       // 64 float4 per row
    const int f4  = (int)(i & 63);

    float4 v = __ldcs(&x4[i]);
    if (mask[row] > 0) {
        const float4* s4 = (const float4*)g_scale;
        const float4* b4 = (const float4*)g_bias;
        float4 s = s4[f4];
        float4 b = b4[f4];
        v.x = fmaf(v.x, s.x, b.x);
        v.y = fmaf(v.y, s.y, b.y);
        v.z = fmaf(v.z, s.z, b.z);
        v.w = fmaf(v.w, s.w, b.w);
    }
    __stcs(&out4[i], v);
}

// ---------------------------------------------------------------------------
extern "C" void kernel_launch(void* const* d_in, const int* in_sizes, int n_in,
                              void* d_out, int out_size) {
    const float* x     = (const float*)d_in[0];
    const int*   mask  = (const int*)d_in[1];
    const float* gamma = (const float*)d_in[2];
    const float* beta  = (const float*)d_in[3];
    float*       out   = (float*)d_out;

    stats_kernel<<<STATS_BLOCKS, STATS_THREADS>>>(x, mask);
    finalize_kernel<<<1, 256>>>(gamma, beta);
    // 32*4096*256 / 4 = 8,388,608 float4 -> 32768 blocks of 256
    apply_kernel<<<32768, 256>>>(x, mask, out);
}